// round 4
// baseline (speedup 1.0000x reference)
#include <cuda_runtime.h>

// x:      (4, 64, 128, 128) fp32  -> 256 independent 128x128 images
// weight: (4, 576, 128, 128) fp32 -> 9 taps per channel, tap k strided by H*W
// steps = 8
//
// Persistent CTAs + cp.async.bulk prefetch + fully fused 8 steps.
// This round: 1024 threads (32 warps), V=1: warp g owns region row g,
// own row kept in registers; smem ping-pong publishes all rows each step.
// Packed fma.rn.f32x2 stencil (18 fma2/thread/step). Boundary zero padding
// folded into lane-0/lane-31 weight registers.

#define H      128
#define W      128
#define IMG    (H * W)
#define STEPS  8
#define TH     16
#define NT     2048
#define SROWS  34
#define RROWS  32

#define OFF_MBAR 0
#define OFF_BUF  1024
#define OFF_WS   (OFF_BUF + 2 * SROWS * W * 4)   // 1024 + 34816  = 35840
#define OFF_XS   (OFF_WS + 9 * RROWS * W * 4)    // + 147456      = 183296
#define SMEM_TOTAL (OFF_XS + RROWS * W * 4)      // + 16384       = 199680

typedef unsigned long long u64;
typedef unsigned int u32;

__device__ __forceinline__ u32 s2u(const void* p) {
    u32 a;
    asm("{ .reg .u64 t; cvta.to.shared.u64 t, %1; cvt.u32.u64 %0, t; }"
        : "=r"(a) : "l"(p));
    return a;
}
__device__ __forceinline__ u64 pk(float lo, float hi) {
    u64 r; asm("mov.b64 %0, {%1,%2};" : "=l"(r) : "f"(lo), "f"(hi)); return r;
}
__device__ __forceinline__ void upk(u64 v, float& lo, float& hi) {
    asm("mov.b64 {%0,%1}, %2;" : "=f"(lo), "=f"(hi) : "l"(v));
}
__device__ __forceinline__ void fma2(u64& d, u64 a, u64 b) {
    asm("fma.rn.f32x2 %0, %1, %2, %0;" : "+l"(d) : "l"(a), "l"(b));
}
__device__ __forceinline__ float shup(float v) { return __shfl_up_sync(0xffffffffu, v, 1); }
__device__ __forceinline__ float shdn(float v) { return __shfl_down_sync(0xffffffffu, v, 1); }

__device__ __forceinline__ void mbar_wait(u32 mbar, u32 parity) {
    asm volatile(
        "{\n\t.reg .pred P;\n\t"
        "W_%=:\n\t"
        "mbarrier.try_wait.parity.shared::cta.b64 P, [%0], %1, 0x989680;\n\t"
        "@P bra.uni D_%=;\n\t"
        "bra.uni W_%=;\n\t"
        "D_%=:\n\t}"
        :: "r"(mbar), "r"(parity) : "memory");
}
__device__ __forceinline__ void bulk_g2s(u32 dst, const void* src, u32 bytes, u32 mbar) {
    asm volatile(
        "cp.async.bulk.shared::cluster.global.mbarrier::complete_tx::bytes "
        "[%0], [%1], %2, [%3];"
        :: "r"(dst), "l"(src), "r"(bytes), "r"(mbar) : "memory");
}

__device__ __forceinline__ void issue_prefetch(int t, const float* x, const float* wgt,
                                               u32 ws, u32 xs, u32 mbar) {
    const int img = t >> 3;
    const int t0  = (t & 7) * TH;
    const int rlo = (t0 - 8 < 0) ? 0 : (t0 - 8);
    const int rhi = (t0 + 24 > H) ? H : (t0 + 24);
    const int nrows = rhi - rlo;
    const int droff = rlo - (t0 - 8);
    const u32 bytes = (u32)nrows * (W * 4);
    asm volatile("mbarrier.arrive.expect_tx.shared.b64 _, [%0], %1;"
                 :: "r"(mbar), "r"(bytes * 10u) : "memory");
#pragma unroll
    for (int k = 0; k < 9; k++) {
        const float* src = wgt + ((size_t)(img * 9 + k) << 14) + rlo * W;
        bulk_g2s(ws + (u32)(k * RROWS + droff) * (W * 4), src, bytes, mbar);
    }
    bulk_g2s(xs + (u32)droff * (W * 4), x + ((size_t)img << 14) + rlo * W, bytes, mbar);
}

__global__ __launch_bounds__(1024, 1)
void diffusion_persist_kernel(const float* __restrict__ x,
                              const float* __restrict__ wgt,
                              float* __restrict__ out)
{
    extern __shared__ char smem[];
    float (*buf)[SROWS][W] = (float (*)[SROWS][W])(smem + OFF_BUF);
    const float* wsp = (const float*)(smem + OFF_WS);
    const float* xsp = (const float*)(smem + OFF_XS);
    const u32 mbar = s2u(smem + OFF_MBAR);
    const u32 ws_a = s2u(smem + OFF_WS);
    const u32 xs_a = s2u(smem + OFF_XS);

    const int tid  = threadIdx.x;
    const int lane = tid & 31;
    const int warp = tid >> 5;          // 0..31; owns region row `warp`
    const int col0 = lane << 2;

    // one-time init: guard rows (region rows -1 and 32 -> zero forever), mbar
    if (tid < 128) {
        int b = tid >> 6, r = (tid >> 5) & 1;
        *(float4*)&buf[b][r ? (SROWS - 1) : 0][col0] = make_float4(0.f, 0.f, 0.f, 0.f);
    }
    if (tid == 0) {
        asm volatile("mbarrier.init.shared.b64 [%0], 1;" :: "r"(mbar) : "memory");
    }
    __syncthreads();

    int t = blockIdx.x;
    const int stride = gridDim.x;
    if (tid == 0 && t < NT) issue_prefetch(t, x, wgt, ws_a, xs_a, mbar);
    u32 ph = 0;

    for (; t < NT; t += stride) {
        mbar_wait(mbar, ph); ph ^= 1u;

        const int img = t >> 3;
        const int t0  = (t & 7) * TH;
        const int grow = t0 - 8 + warp;
        const bool rv  = ((unsigned)grow < (unsigned)H);

        // ---- prologue: normalize this row's 9 taps into packed registers
        // Wp[ki][j]: j = {L01,C01,R01,L23,C23,R23} for vertical tap row ki
        u64 Wp[3][6];
        {
            float aa[9][4];
            if (rv) {
                float s0 = 0.f, s1 = 0.f, s2 = 0.f, s3 = 0.f;
#pragma unroll
                for (int k = 0; k < 9; k++) {
                    float4 tv = *(const float4*)&wsp[(k * RROWS + warp) * W + col0];
                    aa[k][0] = fabsf(tv.x); aa[k][1] = fabsf(tv.y);
                    aa[k][2] = fabsf(tv.z); aa[k][3] = fabsf(tv.w);
                    s0 += aa[k][0]; s1 += aa[k][1]; s2 += aa[k][2]; s3 += aa[k][3];
                }
                const float i0 = __fdividef(1.f, s0), i1 = __fdividef(1.f, s1);
                const float i2 = __fdividef(1.f, s2), i3 = __fdividef(1.f, s3);
#pragma unroll
                for (int k = 0; k < 9; k++) {
                    aa[k][0] *= i0; aa[k][1] *= i1; aa[k][2] *= i2; aa[k][3] *= i3;
                }
                if (lane == 0)  { aa[0][0] = 0.f; aa[3][0] = 0.f; aa[6][0] = 0.f; }
                if (lane == 31) { aa[2][3] = 0.f; aa[5][3] = 0.f; aa[8][3] = 0.f; }
            } else {
#pragma unroll
                for (int k = 0; k < 9; k++) {
                    aa[k][0] = 0.f; aa[k][1] = 0.f; aa[k][2] = 0.f; aa[k][3] = 0.f;
                }
            }
#pragma unroll
            for (int ki = 0; ki < 3; ki++) {
                Wp[ki][0] = pk(aa[ki * 3 + 0][0], aa[ki * 3 + 0][1]);
                Wp[ki][1] = pk(aa[ki * 3 + 1][0], aa[ki * 3 + 1][1]);
                Wp[ki][2] = pk(aa[ki * 3 + 2][0], aa[ki * 3 + 2][1]);
                Wp[ki][3] = pk(aa[ki * 3 + 0][2], aa[ki * 3 + 0][3]);
                Wp[ki][4] = pk(aa[ki * 3 + 1][2], aa[ki * 3 + 1][3]);
                Wp[ki][5] = pk(aa[ki * 3 + 2][2], aa[ki * 3 + 2][3]);
            }
        }

        // x init for this row (zero outside the image)
        float4 y = make_float4(0.f, 0.f, 0.f, 0.f);
        if (rv) y = *(const float4*)&xsp[warp * W + col0];
        *(float4*)&buf[0][warp + 1][col0] = y;
        __syncthreads();   // staging consumed + buf[0] fully published

        // prefetch next tile (overlaps the 8-step loop)
        if (tid == 0 && t + stride < NT)
            issue_prefetch(t + stride, x, wgt, ws_a, xs_a, mbar);

        // ---- 8 fused steps
#pragma unroll
        for (int s = 0; s < STEPS; s++) {
            const int cb = s & 1;
            u64 n01 = 0ull, n23 = 0ull;
            // row above (region row warp-1 = buf row warp)
            {
                float4 v = *(const float4*)&buf[cb][warp][col0];
                const float xl = shup(v.w), xr = shdn(v.x);
                fma2(n01, Wp[0][0], pk(xl, v.x));
                fma2(n01, Wp[0][1], pk(v.x, v.y));
                fma2(n01, Wp[0][2], pk(v.y, v.z));
                fma2(n23, Wp[0][3], pk(v.y, v.z));
                fma2(n23, Wp[0][4], pk(v.z, v.w));
                fma2(n23, Wp[0][5], pk(v.w, xr));
            }
            // own row (registers)
            {
                const float xl = shup(y.w), xr = shdn(y.x);
                fma2(n01, Wp[1][0], pk(xl, y.x));
                fma2(n01, Wp[1][1], pk(y.x, y.y));
                fma2(n01, Wp[1][2], pk(y.y, y.z));
                fma2(n23, Wp[1][3], pk(y.y, y.z));
                fma2(n23, Wp[1][4], pk(y.z, y.w));
                fma2(n23, Wp[1][5], pk(y.w, xr));
            }
            // row below (region row warp+1 = buf row warp+2)
            {
                float4 v = *(const float4*)&buf[cb][warp + 2][col0];
                const float xl = shup(v.w), xr = shdn(v.x);
                fma2(n01, Wp[2][0], pk(xl, v.x));
                fma2(n01, Wp[2][1], pk(v.x, v.y));
                fma2(n01, Wp[2][2], pk(v.y, v.z));
                fma2(n23, Wp[2][3], pk(v.y, v.z));
                fma2(n23, Wp[2][4], pk(v.z, v.w));
                fma2(n23, Wp[2][5], pk(v.w, xr));
            }
            upk(n01, y.x, y.y); upk(n23, y.z, y.w);

            if (s < STEPS - 1) {
                *(float4*)&buf[cb ^ 1][warp + 1][col0] = y;
                __syncthreads();
            }
        }

        // ---- output: warps 8..23 hold the 16 exact rows
        if ((unsigned)(warp - 8) < 16u) {
            *(float4*)(out + (size_t)img * IMG + (t0 + warp - 8) * W + col0) = y;
        }
        // next iter: prologue writes buf[0] only (last buf[0] read was step 6,
        // fenced by its barrier); staging reuse fenced by mbar + post-prologue
        // __syncthreads.
    }
}

extern "C" void kernel_launch(void* const* d_in, const int* in_sizes, int n_in,
                              void* d_out, int out_size)
{
    const float* x   = (const float*)d_in[0];
    const float* wgt = (const float*)d_in[1];
    float* out       = (float*)d_out;

    int sms = 148;
    cudaDeviceGetAttribute(&sms, cudaDevAttrMultiProcessorCount, 0);
    if (sms < 1) sms = 148;
    if (sms > NT) sms = NT;

    cudaFuncSetAttribute(diffusion_persist_kernel,
                         cudaFuncAttributeMaxDynamicSharedMemorySize, SMEM_TOTAL);
    diffusion_persist_kernel<<<sms, 1024, SMEM_TOTAL>>>(x, wgt, out);
}

// round 5
// speedup vs baseline: 1.1523x; 1.1523x over previous
#include <cuda_runtime.h>

// x:      (4, 64, 128, 128) fp32  -> 256 independent 128x128 images
// weight: (4, 576, 128, 128) fp32 -> 9 taps per channel, tap k strided by H*W
// steps = 8
//
// Persistent CTAs (1/SM), 512 threads, V=2 (warp owns region rows 2g,2g+1,
// own rows in registers, neighbors via smem ping-pong), packed fma.rn.f32x2
// stencil, cp.async.bulk double-buffer-free staging prefetched one tile ahead.
// Round 5 deltas vs round 3 (best=64us):
//   - prefetch issue distributed over 10 warps (mbarrier count=10) so no
//     single thread serializes ~10 bulk-copy issues in front of a barrier
//   - flattened step body: all loads -> all shfl -> all packs -> 4 independent
//     fma2 chains (better latency overlap at the phase head)

#define H      128
#define W      128
#define IMG    (H * W)
#define STEPS  8
#define TH     16
#define NT     2048
#define SROWS  34
#define RROWS  32

#define OFF_MBAR 0
#define OFF_BUF  1024
#define OFF_WS   (OFF_BUF + 2 * SROWS * W * 4)   // 1024 + 34816  = 35840
#define OFF_XS   (OFF_WS + 9 * RROWS * W * 4)    // + 147456      = 183296
#define SMEM_TOTAL (OFF_XS + RROWS * W * 4)      // + 16384       = 199680

typedef unsigned long long u64;
typedef unsigned int u32;

__device__ __forceinline__ u32 s2u(const void* p) {
    u32 a;
    asm("{ .reg .u64 t; cvta.to.shared.u64 t, %1; cvt.u32.u64 %0, t; }"
        : "=r"(a) : "l"(p));
    return a;
}
__device__ __forceinline__ u64 pk(float lo, float hi) {
    u64 r; asm("mov.b64 %0, {%1,%2};" : "=l"(r) : "f"(lo), "f"(hi)); return r;
}
__device__ __forceinline__ void upk(u64 v, float& lo, float& hi) {
    asm("mov.b64 {%0,%1}, %2;" : "=f"(lo), "=f"(hi) : "l"(v));
}
__device__ __forceinline__ void fma2(u64& d, u64 a, u64 b) {
    asm("fma.rn.f32x2 %0, %1, %2, %0;" : "+l"(d) : "l"(a), "l"(b));
}
__device__ __forceinline__ float shup(float v) { return __shfl_up_sync(0xffffffffu, v, 1); }
__device__ __forceinline__ float shdn(float v) { return __shfl_down_sync(0xffffffffu, v, 1); }

__device__ __forceinline__ void mbar_wait(u32 mbar, u32 parity) {
    asm volatile(
        "{\n\t.reg .pred P;\n\t"
        "W_%=:\n\t"
        "mbarrier.try_wait.parity.shared::cta.b64 P, [%0], %1, 0x989680;\n\t"
        "@P bra.uni D_%=;\n\t"
        "bra.uni W_%=;\n\t"
        "D_%=:\n\t}"
        :: "r"(mbar), "r"(parity) : "memory");
}
__device__ __forceinline__ void bulk_g2s(u32 dst, const void* src, u32 bytes, u32 mbar) {
    asm volatile(
        "cp.async.bulk.shared::cluster.global.mbarrier::complete_tx::bytes "
        "[%0], [%1], %2, [%3];"
        :: "r"(dst), "l"(src), "r"(bytes), "r"(mbar) : "memory");
}

// Distributed prefetch: issuing thread k (k=0..9) copies one stream.
// k in [0,8]: weight tap k; k==9: x. Each does its own arrive.expect_tx
// (mbarrier init count = 10).
__device__ __forceinline__ void issue_prefetch_k(int t, int k,
                                                 const float* x, const float* wgt,
                                                 u32 ws, u32 xs, u32 mbar) {
    const int img = t >> 3;
    const int t0  = (t & 7) * TH;
    const int rlo = (t0 - 8 < 0) ? 0 : (t0 - 8);
    const int rhi = (t0 + 24 > H) ? H : (t0 + 24);
    const int nrows = rhi - rlo;
    const int droff = rlo - (t0 - 8);
    const u32 bytes = (u32)nrows * (W * 4);
    asm volatile("mbarrier.arrive.expect_tx.shared.b64 _, [%0], %1;"
                 :: "r"(mbar), "r"(bytes) : "memory");
    if (k < 9) {
        const float* src = wgt + ((size_t)(img * 9 + k) << 14) + rlo * W;
        bulk_g2s(ws + (u32)(k * RROWS + droff) * (W * 4), src, bytes, mbar);
    } else {
        bulk_g2s(xs + (u32)droff * (W * 4), x + ((size_t)img << 14) + rlo * W, bytes, mbar);
    }
}

__global__ __launch_bounds__(512, 1)
void diffusion_persist_kernel(const float* __restrict__ x,
                              const float* __restrict__ wgt,
                              float* __restrict__ out)
{
    extern __shared__ char smem[];
    float (*buf)[SROWS][W] = (float (*)[SROWS][W])(smem + OFF_BUF);
    const float* wsp = (const float*)(smem + OFF_WS);
    const float* xsp = (const float*)(smem + OFF_XS);
    const u32 mbar = s2u(smem + OFF_MBAR);
    const u32 ws_a = s2u(smem + OFF_WS);
    const u32 xs_a = s2u(smem + OFF_XS);

    const int tid  = threadIdx.x;
    const int lane = tid & 31;
    const int warp = tid >> 5;          // 0..15; owns region rows 2g, 2g+1
    const int col0 = lane << 2;
    const int g2   = warp * 2;
    const bool issuer = (lane == 0 && warp < 10);

    // one-time init: guard rows (region rows -1 and 32 -> zero forever), mbar
    if (tid < 128) {
        int b = tid >> 6, r = (tid >> 5) & 1;
        *(float4*)&buf[b][r ? (SROWS - 1) : 0][col0] = make_float4(0.f, 0.f, 0.f, 0.f);
    }
    if (tid == 0) {
        asm volatile("mbarrier.init.shared.b64 [%0], 10;" :: "r"(mbar) : "memory");
    }
    __syncthreads();

    int t = blockIdx.x;
    const int stride = gridDim.x;
    if (issuer && t < NT) issue_prefetch_k(t, warp, x, wgt, ws_a, xs_a, mbar);
    u32 ph = 0;

    for (; t < NT; t += stride) {
        mbar_wait(mbar, ph); ph ^= 1u;

        const int img = t >> 3;
        const int t0  = (t & 7) * TH;

        // ---- tile prologue: weights staging -> normalized packed registers
        u64 Wp[2][3][6];
        float4 y0, y1;
#pragma unroll
        for (int ro = 0; ro < 2; ro++) {
            const int rr   = g2 + ro;
            const int grow = t0 - 8 + rr;
            const bool rv  = ((unsigned)grow < (unsigned)H);
            float aa[9][4];
            if (rv) {
                float s0 = 0.f, s1 = 0.f, s2 = 0.f, s3 = 0.f;
#pragma unroll
                for (int k = 0; k < 9; k++) {
                    float4 tv = *(const float4*)&wsp[(k * RROWS + rr) * W + col0];
                    aa[k][0] = fabsf(tv.x); aa[k][1] = fabsf(tv.y);
                    aa[k][2] = fabsf(tv.z); aa[k][3] = fabsf(tv.w);
                    s0 += aa[k][0]; s1 += aa[k][1]; s2 += aa[k][2]; s3 += aa[k][3];
                }
                const float i0 = __fdividef(1.f, s0), i1 = __fdividef(1.f, s1);
                const float i2 = __fdividef(1.f, s2), i3 = __fdividef(1.f, s3);
#pragma unroll
                for (int k = 0; k < 9; k++) {
                    aa[k][0] *= i0; aa[k][1] *= i1; aa[k][2] *= i2; aa[k][3] *= i3;
                }
                if (lane == 0)  { aa[0][0] = 0.f; aa[3][0] = 0.f; aa[6][0] = 0.f; }
                if (lane == 31) { aa[2][3] = 0.f; aa[5][3] = 0.f; aa[8][3] = 0.f; }
            } else {
#pragma unroll
                for (int k = 0; k < 9; k++) {
                    aa[k][0] = 0.f; aa[k][1] = 0.f; aa[k][2] = 0.f; aa[k][3] = 0.f;
                }
            }
#pragma unroll
            for (int ki = 0; ki < 3; ki++) {
                Wp[ro][ki][0] = pk(aa[ki * 3 + 0][0], aa[ki * 3 + 0][1]);
                Wp[ro][ki][1] = pk(aa[ki * 3 + 1][0], aa[ki * 3 + 1][1]);
                Wp[ro][ki][2] = pk(aa[ki * 3 + 2][0], aa[ki * 3 + 2][1]);
                Wp[ro][ki][3] = pk(aa[ki * 3 + 0][2], aa[ki * 3 + 0][3]);
                Wp[ro][ki][4] = pk(aa[ki * 3 + 1][2], aa[ki * 3 + 1][3]);
                Wp[ro][ki][5] = pk(aa[ki * 3 + 2][2], aa[ki * 3 + 2][3]);
            }
            float4 xv = make_float4(0.f, 0.f, 0.f, 0.f);
            if (rv) xv = *(const float4*)&xsp[rr * W + col0];
            if (ro == 0) y0 = xv; else y1 = xv;
            *(float4*)&buf[0][rr + 1][col0] = xv;
        }
        __syncthreads();   // staging consumed + buf[0] published

        // prefetch next tile (distributed; overlaps the 8-step loop)
        if (issuer && t + stride < NT)
            issue_prefetch_k(t + stride, warp, x, wgt, ws_a, xs_a, mbar);

        // ---- 8 fused steps (flattened: loads -> shfls -> packs -> chains)
#pragma unroll
        for (int s = 0; s < STEPS; s++) {
            const int cb = s & 1;
            // phase head: both smem loads first
            float4 va = *(const float4*)&buf[cb][g2][col0];      // row 2g-1
            float4 vb = *(const float4*)&buf[cb][g2 + 3][col0];  // row 2g+2
            // all shuffles (independent of the LDS results for y0/y1)
            const float xl0 = shup(y0.w), xr0 = shdn(y0.x);
            const float xl1 = shup(y1.w), xr1 = shdn(y1.x);
            const float xlA = shup(va.w), xrA = shdn(va.x);
            const float xlB = shup(vb.w), xrB = shdn(vb.x);
            // all packed operands
            const u64 pA0 = pk(xlA, va.x), pA1 = pk(va.x, va.y), pA2 = pk(va.y, va.z);
            const u64 pA3 = pk(va.z, va.w), pA4 = pk(va.w, xrA);
            const u64 p00 = pk(xl0, y0.x), p01 = pk(y0.x, y0.y), p02 = pk(y0.y, y0.z);
            const u64 p03 = pk(y0.z, y0.w), p04 = pk(y0.w, xr0);
            const u64 p10 = pk(xl1, y1.x), p11 = pk(y1.x, y1.y), p12 = pk(y1.y, y1.z);
            const u64 p13 = pk(y1.z, y1.w), p14 = pk(y1.w, xr1);
            const u64 pB0 = pk(xlB, vb.x), pB1 = pk(vb.x, vb.y), pB2 = pk(vb.y, vb.z);
            const u64 pB3 = pk(vb.z, vb.w), pB4 = pk(vb.w, xrB);

            // 4 independent accumulation chains
            u64 n001 = 0ull, n023 = 0ull, n101 = 0ull, n123 = 0ull;
            fma2(n001, Wp[0][0][0], pA0); fma2(n023, Wp[0][0][3], pA2);
            fma2(n101, Wp[1][0][0], p00); fma2(n123, Wp[1][0][3], p02);
            fma2(n001, Wp[0][0][1], pA1); fma2(n023, Wp[0][0][4], pA3);
            fma2(n101, Wp[1][0][1], p01); fma2(n123, Wp[1][0][4], p03);
            fma2(n001, Wp[0][0][2], pA2); fma2(n023, Wp[0][0][5], pA4);
            fma2(n101, Wp[1][0][2], p02); fma2(n123, Wp[1][0][5], p04);

            fma2(n001, Wp[0][1][0], p00); fma2(n023, Wp[0][1][3], p02);
            fma2(n101, Wp[1][1][0], p10); fma2(n123, Wp[1][1][3], p12);
            fma2(n001, Wp[0][1][1], p01); fma2(n023, Wp[0][1][4], p03);
            fma2(n101, Wp[1][1][1], p11); fma2(n123, Wp[1][1][4], p13);
            fma2(n001, Wp[0][1][2], p02); fma2(n023, Wp[0][1][5], p04);
            fma2(n101, Wp[1][1][2], p12); fma2(n123, Wp[1][1][5], p14);

            fma2(n001, Wp[0][2][0], p10); fma2(n023, Wp[0][2][3], p12);
            fma2(n101, Wp[1][2][0], pB0); fma2(n123, Wp[1][2][3], pB2);
            fma2(n001, Wp[0][2][1], p11); fma2(n023, Wp[0][2][4], p13);
            fma2(n101, Wp[1][2][1], pB1); fma2(n123, Wp[1][2][4], pB3);
            fma2(n001, Wp[0][2][2], p12); fma2(n023, Wp[0][2][5], p14);
            fma2(n101, Wp[1][2][2], pB2); fma2(n123, Wp[1][2][5], pB4);

            upk(n001, y0.x, y0.y); upk(n023, y0.z, y0.w);
            upk(n101, y1.x, y1.y); upk(n123, y1.z, y1.w);

            if (s < STEPS - 1) {
                const int nb = cb ^ 1;
                *(float4*)&buf[nb][g2 + 1][col0] = y0;
                *(float4*)&buf[nb][g2 + 2][col0] = y1;
                __syncthreads();
            }
        }

        // ---- output: warps 4..11 hold the 16 exact rows (region rows 8..23)
        if ((unsigned)(warp - 4) < 8u) {
            float* ob = out + (size_t)img * IMG + (t0 + g2 - 8) * W + col0;
            *(float4*)ob       = y0;
            *(float4*)(ob + W) = y1;
        }
    }
}

extern "C" void kernel_launch(void* const* d_in, const int* in_sizes, int n_in,
                              void* d_out, int out_size)
{
    const float* x   = (const float*)d_in[0];
    const float* wgt = (const float*)d_in[1];
    float* out       = (float*)d_out;

    int sms = 148;
    cudaDeviceGetAttribute(&sms, cudaDevAttrMultiProcessorCount, 0);
    if (sms < 1) sms = 148;
    if (sms > NT) sms = NT;

    cudaFuncSetAttribute(diffusion_persist_kernel,
                         cudaFuncAttributeMaxDynamicSharedMemorySize, SMEM_TOTAL);
    diffusion_persist_kernel<<<sms, 512, SMEM_TOTAL>>>(x, wgt, out);
}